// round 15
// baseline (speedup 1.0000x reference)
#include <cuda_runtime.h>
#include <cuda_bf16.h>
#include <cstdint>

// ---------------------------------------------------------------------------
// CTRGC round 15: warp-specialized single-barrier pipeline.
//  TT=5 (20 YA strips exactly) -> YA and staging DOUBLE-BUFFERED in smem.
//  Per phase (ONE __syncthreads): warps 0-11 run stage A(tile i);
//  warps 12-15 run stage B(tile i-1) + pack staging(tile i+1).
//  W fragments streamed from global (L2). MMA order identical to R11/R14.
// ---------------------------------------------------------------------------

#define TFULL 256
#define CIN 64
#define VD 18
#define TT 5
#define TILES_PER_N 52
#define NTILES 6656            // 128 * 52
#define THREADS 512
#define GRID 148
#define STP 100                // staging row pitch (words), conflict-free

// ---- smem byte offsets ----
#define OFF_M   0                          // M' uint4: 6144
#define OFF_ST  6144                       // staging: 2 x 64*100*4 = 2 x 25600
#define STG_BUF 25600
#define OFF_YA  57344                      // YA: 2 x (20 strips hi 40960 + lo 40960)
#define YA_BUF  81920
#define YA_HALF 40960
#define SMEM_BYTES 221184

// prepped parameters (device globals)
__device__ uint4 d_WfH[12 * 4 * 32];
__device__ uint4 d_WfL[12 * 4 * 32];
__device__ uint4 d_Mf[12 * 32];            // (bh0, bl0, bh1, bl1)
__device__ float d_Cf[64];

__device__ __forceinline__ uint32_t pack2bf(float x, float y) {
    __nv_bfloat162 t = __floats2bfloat162_rn(x, y);   // x -> low half
    return *reinterpret_cast<uint32_t*>(&t);
}

// pack one float into (lo_bf16 << 16) | hi_bf16
__device__ __forceinline__ uint32_t pack_hl(float v) {
    __nv_bfloat16 hb = __float2bfloat16(v);
    float hf = __bfloat162float(hb);
    __nv_bfloat16 lb = __float2bfloat16(v - hf);
    uint16_t hbits = *reinterpret_cast<uint16_t*>(&hb);
    uint16_t lbits = *reinterpret_cast<uint16_t*>(&lb);
    return ((uint32_t)lbits << 16) | hbits;
}

// M'[kc][w]: kc<54 -> M_{kc/18}[kc%18][w]; kc==54 -> 1 (bias lane); else 0.
__device__ float mprime(const float* A, const float* PA, int kc, int w) {
    if (w >= VD) return 0.0f;
    if (kc < 54) {
        int k = kc / 18, v = kc - 18 * k;
        return A[(k * VD + v) * VD + w] + PA[(k * VD + v) * VD + w];
    }
    return (kc == 54) ? 1.0f : 0.0f;
}

__global__ void prep_kernel(const float* __restrict__ A, const float* __restrict__ PA,
                            const float* __restrict__ Wta, const float* __restrict__ bta,
                            const float* __restrict__ g_ta, const float* __restrict__ b_ta,
                            const float* __restrict__ m_ta, const float* __restrict__ v_ta,
                            const float* __restrict__ g_bn, const float* __restrict__ b_bn,
                            const float* __restrict__ m_bn, const float* __restrict__ v_bn)
{
    int tid = threadIdx.x;
    for (int idx = tid; idx < 12 * 4 * 32; idx += blockDim.x) {
        int strip = idx >> 7;
        int ks = (idx >> 5) & 3;
        int lane = idx & 31;
        int g = lane >> 2, tig = lane & 3;
        int c0 = ks * 16 + 2 * tig;
        float vals[8];
#pragma unroll
        for (int e = 0; e < 8; e++) {
            int row = strip * 16 + g + ((e >> 1) & 1) * 8;
            int c = c0 + (e & 1) + (e >> 2) * 8;
            int k = row >> 6, o = row & 63;
            float s2 = g_bn[o] * rsqrtf(v_bn[o] + 1e-5f);
            float s1 = g_ta[k * 64 + o] * rsqrtf(v_ta[k * 64 + o] + 1e-5f);
            vals[e] = s2 * s1 * Wta[(k * 64 + o) * 64 + c];
        }
        float hf[8], lf[8];
#pragma unroll
        for (int e = 0; e < 8; e++) {
            __nv_bfloat16 h = __float2bfloat16(vals[e]);
            hf[e] = __bfloat162float(h);
            lf[e] = vals[e] - hf[e];
        }
        d_WfH[idx] = make_uint4(pack2bf(hf[0], hf[1]), pack2bf(hf[2], hf[3]),
                                pack2bf(hf[4], hf[5]), pack2bf(hf[6], hf[7]));
        d_WfL[idx] = make_uint4(pack2bf(lf[0], lf[1]), pack2bf(lf[2], lf[3]),
                                pack2bf(lf[4], lf[5]), pack2bf(lf[6], lf[7]));
    }
    for (int idx = tid; idx < 12 * 32; idx += blockDim.x) {
        int nb = idx >> 7;
        int ks = (idx >> 5) & 3;
        int lane = idx & 31;
        int g = lane >> 2, tig = lane & 3;
        int wcol = nb * 8 + g;
        int kc0 = ks * 16 + 2 * tig;
        float vals[4] = { mprime(A, PA, kc0, wcol),     mprime(A, PA, kc0 + 1, wcol),
                          mprime(A, PA, kc0 + 8, wcol), mprime(A, PA, kc0 + 9, wcol) };
        float hf[4], lf[4];
#pragma unroll
        for (int e = 0; e < 4; e++) {
            __nv_bfloat16 h = __float2bfloat16(vals[e]);
            hf[e] = __bfloat162float(h);
            lf[e] = vals[e] - hf[e];
        }
        d_Mf[idx] = make_uint4(pack2bf(hf[0], hf[1]), pack2bf(lf[0], lf[1]),
                               pack2bf(hf[2], hf[3]), pack2bf(lf[2], lf[3]));
    }
    if (tid < 64) {
        int o = tid;
        float s2 = g_bn[o] * rsqrtf(v_bn[o] + 1e-5f);
        float acc = 0.0f;
        for (int k = 0; k < 3; k++) {
            float s1 = g_ta[k * 64 + o] * rsqrtf(v_ta[k * 64 + o] + 1e-5f);
            acc += s1 * (bta[k * 64 + o] - m_ta[k * 64 + o]) + b_ta[k * 64 + o];
        }
        d_Cf[o] = s2 * acc + b_bn[o] - m_bn[o] * s2;
    }
}

// ---- HMMA m16n8k16 bf16, f32 accum ----
__device__ __forceinline__ void mma_bf16(float* d, uint32_t a0, uint32_t a1,
                                         uint32_t a2, uint32_t a3,
                                         uint32_t b0, uint32_t b1) {
    asm("mma.sync.aligned.m16n8k16.row.col.f32.bf16.bf16.f32 "
        "{%0,%1,%2,%3},{%4,%5,%6,%7},{%8,%9},{%0,%1,%2,%3};"
        : "+f"(d[0]), "+f"(d[1]), "+f"(d[2]), "+f"(d[3])
        : "r"(a0), "r"(a1), "r"(a2), "r"(a3), "r"(b0), "r"(b1));
}

extern __shared__ char smem[];

// YA word: ((frag*4 + reg) * 32 + lane) ; frag = strip2*4 + ks2 (20 strips)
__device__ __forceinline__ int ya_off(int frag, int reg, int lane) {
    return (((frag * 4 + reg) * 32) + lane) * 4;
}

__device__ __forceinline__ void ya_write(char* baseH, char* baseL,
                                         int row2, int kcol, float d0, float d1) {
    int strip2 = row2 >> 4, r2 = row2 & 15;
    int ks2 = kcol >> 4, cc2 = kcol & 15;
    int lane2 = (r2 & 7) * 4 + ((cc2 >> 1) & 3);
    int reg2 = (r2 >> 3) + 2 * (cc2 >> 3);
    int off = ya_off(strip2 * 4 + ks2, reg2, lane2);
    __nv_bfloat16 h0 = __float2bfloat16(d0);
    __nv_bfloat16 h1 = __float2bfloat16(d1);
    float h0f = __bfloat162float(h0), h1f = __bfloat162float(h1);
    *reinterpret_cast<uint32_t*>(baseH + off) = pack2bf(h0f, h1f);
    *reinterpret_cast<uint32_t*>(baseL + off) = pack2bf(d0 - h0f, d1 - h1f);
}

__global__ __launch_bounds__(THREADS, 1)
void ctrgc15(const float* __restrict__ x, float* __restrict__ out)
{
    const int tid = threadIdx.x;
    const int w = tid >> 5;      // warp 0..15
    const int lane = tid & 31;
    const int g = lane >> 2;
    const int tig = lane & 3;

    // ---- one-time init ----
    {
        uint4* mf = reinterpret_cast<uint4*>(smem + OFF_M);
        for (int i = tid; i < 12 * 32; i += THREADS) mf[i] = d_Mf[i];
        uint32_t* ya = reinterpret_cast<uint32_t*>(smem + OFF_YA);
        for (int i = tid; i < 2 * YA_BUF / 4; i += THREADS) ya[i] = 0u;
    }
    __syncthreads();
    if (tid < 320) {             // bias column kcol=54 into both YA buffers
        float cf = d_Cf[tid & 63];
        ya_write(smem + OFF_YA, smem + OFF_YA + YA_HALF, tid, 54, cf, 0.0f);
        ya_write(smem + OFF_YA + YA_BUF, smem + OFF_YA + YA_BUF + YA_HALF, tid, 54, cf, 0.0f);
    }

    // ---- prologue: pack tile (blockIdx.x) into staging buf 0 (all threads) ----
    {
        int i0 = blockIdx.x;
        int n = i0 / TILES_PER_N;
        int t0 = (i0 - n * TILES_PER_N) * TT;
        int nvalid = ((t0 + TT <= TFULL) ? TT : (TFULL - t0)) * VD;
        const float* xs = x + (size_t)n * (CIN * TFULL * VD) + (size_t)t0 * VD;
        char* stg0 = smem + OFF_ST;
#pragma unroll
        for (int m = 0; m < 12; m++) {
            int idx = tid + m * THREADS;   // 0..6143
            int c = idx / 96, p = idx - 96 * c;
            uint32_t pv = (p < nvalid) ? pack_hl(__ldg(xs + c * (TFULL * VD) + p)) : 0u;
            *reinterpret_cast<uint32_t*>(stg0 + (c * STP + p) * 4) = pv;
        }
    }
    __syncthreads();

    for (int j = 0; ; j++) {
        const int iA = blockIdx.x + j * GRID;
        const bool hasA = (iA < NTILES);
        const bool hasB = (j > 0) && (iA - GRID < NTILES);
        if (!hasA && !hasB) break;

        char* stgR = smem + OFF_ST + (j & 1) * STG_BUF;
        char* stgW = smem + OFF_ST + ((j + 1) & 1) * STG_BUF;
        char* yaWH = smem + OFF_YA + (j & 1) * YA_BUF;
        char* yaWL = yaWH + YA_HALF;
        char* yaRH = smem + OFF_YA + ((j + 1) & 1) * YA_BUF;   // == (j-1)&1
        char* yaRL = yaRH + YA_HALF;

        if (w < 12) {
            // =================== A-role: stage A(iA) ========================
            if (hasA) {
                const int sg = w & 3;    // strips {sg, sg+4, sg+8}
                const int pg = w >> 2;   // pbs {pg, pg+3, pg+6, pg+9}

                // build xb for 4 posblocks from staging (LDS + PRMT)
                uint2 xbh[4][4], xbl[4][4];
#pragma unroll
                for (int p_i = 0; p_i < 4; p_i++) {
                    const int pos = (pg + 3 * p_i) * 8 + g;
#pragma unroll
                    for (int ks = 0; ks < 4; ks++) {
                        const int c0 = ks * 16 + 2 * tig;
                        uint32_t q00 = *reinterpret_cast<const uint32_t*>(stgR + (c0 * STP + pos) * 4);
                        uint32_t q01 = *reinterpret_cast<const uint32_t*>(stgR + ((c0 + 1) * STP + pos) * 4);
                        uint32_t q10 = *reinterpret_cast<const uint32_t*>(stgR + ((c0 + 8) * STP + pos) * 4);
                        uint32_t q11 = *reinterpret_cast<const uint32_t*>(stgR + ((c0 + 9) * STP + pos) * 4);
                        xbh[p_i][ks].x = __byte_perm(q00, q01, 0x5410);
                        xbl[p_i][ks].x = __byte_perm(q00, q01, 0x7632);
                        xbh[p_i][ks].y = __byte_perm(q10, q11, 0x5410);
                        xbl[p_i][ks].y = __byte_perm(q10, q11, 0x7632);
                    }
                }
#pragma unroll
                for (int s_i = 0; s_i < 3; s_i++) {
                    const int s = sg + 4 * s_i;
                    uint4 ah[4], al[4];
#pragma unroll
                    for (int ks = 0; ks < 4; ks++) {
                        ah[ks] = __ldg(&d_WfH[(s * 4 + ks) * 32 + lane]);
                        al[ks] = __ldg(&d_WfL[(s * 4 + ks) * 32 + lane]);
                    }
                    const int rowA0 = s * 16 + g;
                    const int k0 = rowA0 >> 6, o0 = rowA0 & 63;
                    const int rowA1 = rowA0 + 8;
                    const int k1 = rowA1 >> 6, o1 = rowA1 & 63;
#pragma unroll
                    for (int p_i = 0; p_i < 4; p_i++) {
                        const int p0 = (pg + 3 * p_i) * 8 + 2 * tig;
                        float D[4] = {0.0f, 0.0f, 0.0f, 0.0f};
#pragma unroll
                        for (int ks = 0; ks < 4; ks++) {
                            mma_bf16(D, ah[ks].x, ah[ks].y, ah[ks].z, ah[ks].w,
                                     xbh[p_i][ks].x, xbh[p_i][ks].y);
                            mma_bf16(D, ah[ks].x, ah[ks].y, ah[ks].z, ah[ks].w,
                                     xbl[p_i][ks].x, xbl[p_i][ks].y);
                            mma_bf16(D, al[ks].x, al[ks].y, al[ks].z, al[ks].w,
                                     xbh[p_i][ks].x, xbh[p_i][ks].y);
                        }
                        if (p0 < 90) {
                            int tloc = (p0 * 228) >> 12;
                            int vloc = p0 - 18 * tloc;
                            ya_write(yaWH, yaWL, tloc * 64 + o0, k0 * 18 + vloc, D[0], D[1]);
                            ya_write(yaWH, yaWL, tloc * 64 + o1, k1 * 18 + vloc, D[2], D[3]);
                        }
                    }
                }
            }
        } else {
            // ============ B-role: stage B(iA-148) + pack staging(iA+148) ====
            const int bw = w - 12;   // 0..3
            if (hasB) {
                const int iB = iA - GRID;
                const int nB = iB / TILES_PER_N;
                const int t0B = (iB - nB * TILES_PER_N) * TT;
                const int validB = (t0B + TT <= TFULL) ? TT : (TFULL - t0B);
                uint4 mf[3][4];
#pragma unroll
                for (int nb = 0; nb < 3; nb++)
#pragma unroll
                    for (int ks = 0; ks < 4; ks++)
                        mf[nb][ks] = *reinterpret_cast<const uint4*>(
                            smem + OFF_M + (((nb * 4 + ks) * 32 + lane) << 4));
#pragma unroll
                for (int st_i = 0; st_i < 5; st_i++) {
                    const int si = bw + 4 * st_i;      // 0..19
                    uint4 ah[4], al[4];
#pragma unroll
                    for (int ks = 0; ks < 4; ks++) {
                        int f = si * 4 + ks;
                        ah[ks].x = *reinterpret_cast<const uint32_t*>(yaRH + ya_off(f, 0, lane));
                        ah[ks].y = *reinterpret_cast<const uint32_t*>(yaRH + ya_off(f, 1, lane));
                        ah[ks].z = *reinterpret_cast<const uint32_t*>(yaRH + ya_off(f, 2, lane));
                        ah[ks].w = *reinterpret_cast<const uint32_t*>(yaRH + ya_off(f, 3, lane));
                        al[ks].x = *reinterpret_cast<const uint32_t*>(yaRL + ya_off(f, 0, lane));
                        al[ks].y = *reinterpret_cast<const uint32_t*>(yaRL + ya_off(f, 1, lane));
                        al[ks].z = *reinterpret_cast<const uint32_t*>(yaRL + ya_off(f, 2, lane));
                        al[ks].w = *reinterpret_cast<const uint32_t*>(yaRL + ya_off(f, 3, lane));
                    }
                    const int rowB = si * 16 + g;
                    const int tB = rowB >> 6;
                    const int oB = rowB & 63;
#pragma unroll
                    for (int nb = 0; nb < 3; nb++) {
                        float D2[4] = {0.0f, 0.0f, 0.0f, 0.0f};
#pragma unroll
                        for (int ks = 0; ks < 4; ks++) {
                            mma_bf16(D2, ah[ks].x, ah[ks].y, ah[ks].z, ah[ks].w,
                                     mf[nb][ks].x, mf[nb][ks].z);
                            mma_bf16(D2, ah[ks].x, ah[ks].y, ah[ks].z, ah[ks].w,
                                     mf[nb][ks].y, mf[nb][ks].w);
                            mma_bf16(D2, al[ks].x, al[ks].y, al[ks].z, al[ks].w,
                                     mf[nb][ks].x, mf[nb][ks].z);
                        }
                        int w0 = nb * 8 + 2 * tig;
                        if (w0 < VD && tB < validB) {
                            size_t base = ((size_t)(nB * 64 + oB) * TFULL + (t0B + tB)) * VD + w0;
                            *reinterpret_cast<float2*>(out + base) =
                                make_float2(fmaxf(D2[0], 0.0f), fmaxf(D2[1], 0.0f));
                            size_t base2 = base + (size_t)8 * TFULL * VD;   // o+8
                            *reinterpret_cast<float2*>(out + base2) =
                                make_float2(fmaxf(D2[2], 0.0f), fmaxf(D2[3], 0.0f));
                        }
                    }
                }
            }
            // pack staging for tile iA+148
            const int iN = iA + GRID;
            if (iN < NTILES) {
                const int nN = iN / TILES_PER_N;
                const int t0N = (iN - nN * TILES_PER_N) * TT;
                const int nvN = ((t0N + TT <= TFULL) ? TT : (TFULL - t0N)) * VD;
                const float* xs = x + (size_t)nN * (CIN * TFULL * VD) + (size_t)t0N * VD;
#pragma unroll
                for (int m = 0; m < 48; m++) {
                    int idx = (bw * 32 + lane) + m * 128;  // 0..6143
                    int c = idx / 96, p = idx - 96 * c;
                    uint32_t pv = (p < nvN) ? pack_hl(__ldg(xs + c * (TFULL * VD) + p)) : 0u;
                    *reinterpret_cast<uint32_t*>(stgW + (c * STP + p) * 4) = pv;
                }
            }
        }
        __syncthreads();
    }
}

extern "C" void kernel_launch(void* const* d_in, const int* in_sizes, int n_in,
                              void* d_out, int out_size)
{
    (void)in_sizes; (void)n_in; (void)out_size;
    const float* x    = (const float*)d_in[0];
    const float* A    = (const float*)d_in[1];
    const float* PA   = (const float*)d_in[2];
    const float* Wta  = (const float*)d_in[3];
    const float* bta  = (const float*)d_in[4];
    const float* g_ta = (const float*)d_in[5];
    const float* b_ta = (const float*)d_in[6];
    const float* m_ta = (const float*)d_in[7];
    const float* v_ta = (const float*)d_in[8];
    // d_in[9..12] dead attention branch
    const float* g_bn = (const float*)d_in[13];
    const float* b_bn = (const float*)d_in[14];
    const float* m_bn = (const float*)d_in[15];
    const float* v_bn = (const float*)d_in[16];
    float* out = (float*)d_out;

    cudaFuncSetAttribute(ctrgc15, cudaFuncAttributeMaxDynamicSharedMemorySize, SMEM_BYTES);

    prep_kernel<<<1, 256>>>(A, PA, Wta, bta, g_ta, b_ta, m_ta, v_ta,
                            g_bn, b_bn, m_bn, v_bn);
    ctrgc15<<<GRID, THREADS, SMEM_BYTES>>>(x, out);
}

// round 16
// speedup vs baseline: 2.1963x; 2.1963x over previous
#include <cuda_runtime.h>
#include <cuda_bf16.h>
#include <cstdint>

// ---------------------------------------------------------------------------
// CTRGC final: round-8 kernel (empirical optimum, 242.4us).
// Dual-GEMM on tensor cores (mma.sync m16n8k16 bf16, 3-term hi/lo split):
//   stage A: Y[(k,o),pos] = Weff * X   (4x4 warp blocking, frags SoA in smem)
//   stage B: out[(t,o),w] = Yr * M'    (bias folded as K-column 54)
// 2-phase tile schedule, LDG prefetch overlapped with stage B.
// ---------------------------------------------------------------------------

#define TFULL 256
#define CIN 64
#define VD 18
#define TT 7
#define TILES_PER_N 37
#define TILES_PER_CTA 32
#define THREADS 512
#define GRID 148

// ---- smem byte offsets ----
#define OFF_WAH 0                          // W A-frags hi: 12*4*32*16 = 24576
#define OFF_WAL (OFF_WAH + 12*4*32*16)     // 24576
#define OFF_XBH (OFF_WAL + 12*4*32*16)     // X B-frags hi (SoA): 16*4*2*32*4 = 16384
#define OFF_XBL (OFF_XBH + 16*4*2*32*4)
#define OFF_YAH (OFF_XBL + 16*4*2*32*4)    // Y A-frags hi (SoA): 28*4*4*32*4 = 57344
#define OFF_YAL (OFF_YAH + 28*4*4*32*4)
#define OFF_MBH (OFF_YAL + 28*4*4*32*4)    // M' B-frags hi: 3*4*32*8 = 3072
#define OFF_MBL (OFF_MBH + 3*4*32*8)
#define SMEM_BYTES (OFF_MBL + 3*4*32*8)    // 202752

// prepped parameters (device globals)
__device__ uint4 d_WfH[12 * 4 * 32];
__device__ uint4 d_WfL[12 * 4 * 32];
__device__ unsigned long long d_MfH[3 * 4 * 32];
__device__ unsigned long long d_MfL[3 * 4 * 32];
__device__ float d_Cf[64];

__device__ __forceinline__ uint32_t pack2bf(float x, float y) {
    __nv_bfloat162 t = __floats2bfloat162_rn(x, y);   // x -> low half
    return *reinterpret_cast<uint32_t*>(&t);
}

// M'[kc][w]: kc<54 -> M_{kc/18}[kc%18][w]; kc==54 -> 1 (bias lane); else 0.
__device__ float mprime(const float* A, const float* PA, int kc, int w) {
    if (w >= VD) return 0.0f;
    if (kc < 54) {
        int k = kc / 18, v = kc - 18 * k;
        return A[(k * VD + v) * VD + w] + PA[(k * VD + v) * VD + w];
    }
    return (kc == 54) ? 1.0f : 0.0f;
}

__global__ void prep_kernel(const float* __restrict__ A, const float* __restrict__ PA,
                            const float* __restrict__ Wta, const float* __restrict__ bta,
                            const float* __restrict__ g_ta, const float* __restrict__ b_ta,
                            const float* __restrict__ m_ta, const float* __restrict__ v_ta,
                            const float* __restrict__ g_bn, const float* __restrict__ b_bn,
                            const float* __restrict__ m_bn, const float* __restrict__ v_bn)
{
    int tid = threadIdx.x;
    // ---- W A-fragments: rows (k,o) 192 = 12 strips, K = c (64, 4 ks) ----
    for (int idx = tid; idx < 12 * 4 * 32; idx += blockDim.x) {
        int strip = idx >> 7;
        int ks = (idx >> 5) & 3;
        int lane = idx & 31;
        int g = lane >> 2, tig = lane & 3;
        int c0 = ks * 16 + 2 * tig;
        float vals[8];
#pragma unroll
        for (int e = 0; e < 8; e++) {
            int row = strip * 16 + g + ((e >> 1) & 1) * 8;
            int c = c0 + (e & 1) + (e >> 2) * 8;
            int k = row >> 6, o = row & 63;
            float s2 = g_bn[o] * rsqrtf(v_bn[o] + 1e-5f);
            float s1 = g_ta[k * 64 + o] * rsqrtf(v_ta[k * 64 + o] + 1e-5f);
            vals[e] = s2 * s1 * Wta[(k * 64 + o) * 64 + c];
        }
        float hf[8], lf[8];
#pragma unroll
        for (int e = 0; e < 8; e++) {
            __nv_bfloat16 h = __float2bfloat16(vals[e]);
            hf[e] = __bfloat162float(h);
            lf[e] = vals[e] - hf[e];
        }
        d_WfH[idx] = make_uint4(pack2bf(hf[0], hf[1]), pack2bf(hf[2], hf[3]),
                                pack2bf(hf[4], hf[5]), pack2bf(hf[6], hf[7]));
        d_WfL[idx] = make_uint4(pack2bf(lf[0], lf[1]), pack2bf(lf[2], lf[3]),
                                pack2bf(lf[4], lf[5]), pack2bf(lf[6], lf[7]));
    }
    // ---- M' B-fragments ----
    for (int idx = tid; idx < 3 * 4 * 32; idx += blockDim.x) {
        int nb = idx >> 7;
        int ks = (idx >> 5) & 3;
        int lane = idx & 31;
        int g = lane >> 2, tig = lane & 3;
        int wcol = nb * 8 + g;
        int kc0 = ks * 16 + 2 * tig;
        float vals[4] = { mprime(A, PA, kc0, wcol),     mprime(A, PA, kc0 + 1, wcol),
                          mprime(A, PA, kc0 + 8, wcol), mprime(A, PA, kc0 + 9, wcol) };
        float hf[4], lf[4];
#pragma unroll
        for (int e = 0; e < 4; e++) {
            __nv_bfloat16 h = __float2bfloat16(vals[e]);
            hf[e] = __bfloat162float(h);
            lf[e] = vals[e] - hf[e];
        }
        d_MfH[idx] = ((unsigned long long)pack2bf(hf[2], hf[3]) << 32) | pack2bf(hf[0], hf[1]);
        d_MfL[idx] = ((unsigned long long)pack2bf(lf[2], lf[3]) << 32) | pack2bf(lf[0], lf[1]);
    }
    // ---- folded bias ----
    if (tid < 64) {
        int o = tid;
        float s2 = g_bn[o] * rsqrtf(v_bn[o] + 1e-5f);
        float acc = 0.0f;
        for (int k = 0; k < 3; k++) {
            float s1 = g_ta[k * 64 + o] * rsqrtf(v_ta[k * 64 + o] + 1e-5f);
            acc += s1 * (bta[k * 64 + o] - m_ta[k * 64 + o]) + b_ta[k * 64 + o];
        }
        d_Cf[o] = s2 * acc + b_bn[o] - m_bn[o] * s2;
    }
}

// ---- HMMA m16n8k16 bf16, f32 accum ----
__device__ __forceinline__ void mma_bf16(float* d, uint32_t a0, uint32_t a1,
                                         uint32_t a2, uint32_t a3,
                                         uint32_t b0, uint32_t b1) {
    asm("mma.sync.aligned.m16n8k16.row.col.f32.bf16.bf16.f32 "
        "{%0,%1,%2,%3},{%4,%5,%6,%7},{%8,%9},{%0,%1,%2,%3};"
        : "+f"(d[0]), "+f"(d[1]), "+f"(d[2]), "+f"(d[3])
        : "r"(a0), "r"(a1), "r"(a2), "r"(a3), "r"(b0), "r"(b1));
}

extern __shared__ char smem[];

// SoA word address helpers (byte offsets)
// YA: word = ((frag*4 + reg) * 32 + lane) ; frag = strip2*4 + ks2
__device__ __forceinline__ int ya_off(int frag, int reg, int lane) {
    return (((frag * 4 + reg) * 32) + lane) * 4;
}
// XB: word = ((frag*2 + reg) * 32 + lane) ; frag = pb*4 + ks
__device__ __forceinline__ int xb_off(int frag, int reg, int lane) {
    return (((frag * 2 + reg) * 32) + lane) * 4;
}

// write one (row2, kcol even pair) bf16 hi/lo into stage-B A-frag buffers
__device__ __forceinline__ void ya_write(int row2, int kcol, float d0, float d1) {
    int strip2 = row2 >> 4, r2 = row2 & 15;
    int ks2 = kcol >> 4, cc2 = kcol & 15;
    int lane2 = (r2 & 7) * 4 + ((cc2 >> 1) & 3);
    int reg2 = (r2 >> 3) + 2 * (cc2 >> 3);
    int off = ya_off(strip2 * 4 + ks2, reg2, lane2);
    __nv_bfloat16 h0 = __float2bfloat16(d0);
    __nv_bfloat16 h1 = __float2bfloat16(d1);
    float h0f = __bfloat162float(h0), h1f = __bfloat162float(h1);
    *reinterpret_cast<uint32_t*>(smem + OFF_YAH + off) = pack2bf(h0f, h1f);
    *reinterpret_cast<uint32_t*>(smem + OFF_YAL + off) = pack2bf(d0 - h0f, d1 - h1f);
}

__global__ __launch_bounds__(THREADS, 1)
void ctrgc16(const float* __restrict__ x, float* __restrict__ out)
{
    const int tid = threadIdx.x;
    const int w = tid >> 5;      // warp 0..15
    const int lane = tid & 31;
    const int g = lane >> 2;
    const int tig = lane & 3;

    // ---- one-time init ----
    {
        uint4* wh = reinterpret_cast<uint4*>(smem + OFF_WAH);
        uint4* wl = reinterpret_cast<uint4*>(smem + OFF_WAL);
        for (int i = tid; i < 12 * 4 * 32; i += THREADS) { wh[i] = d_WfH[i]; wl[i] = d_WfL[i]; }
        unsigned long long* mh = reinterpret_cast<unsigned long long*>(smem + OFF_MBH);
        unsigned long long* ml = reinterpret_cast<unsigned long long*>(smem + OFF_MBL);
        for (int i = tid; i < 3 * 4 * 32; i += THREADS) { mh[i] = d_MfH[i]; ml[i] = d_MfL[i]; }
        uint32_t* ya = reinterpret_cast<uint32_t*>(smem + OFF_YAH);
        for (int i = tid; i < (2 * 28 * 4 * 4 * 32); i += THREADS) ya[i] = 0u;
    }
    __syncthreads();
    // bias column kcol=54: Y[row2][54] = Cf[o]  (pair (54,55), 55 stays 0)
    if (tid < 448) {
        float cf = d_Cf[tid & 63];
        ya_write(tid, 54, cf, 0.0f);
    }
    __syncthreads();

    const int tile0 = blockIdx.x * TILES_PER_CTA;

    // conversion lane constants
    const int cv_pos = w * 8 + g;
    const int cv_cbase = 2 * tig;

    // ---- prologue: convert tile0 into X B-frags (SoA) ----
    {
        int n = tile0 / TILES_PER_N;
        int j = tile0 - n * TILES_PER_N;
        int t0 = j * TT;
        int nvalid = ((t0 + TT <= TFULL) ? TT : (TFULL - t0)) * VD;
        const float* xb = x + (size_t)n * (CIN * TFULL * VD) + (size_t)t0 * VD;
#pragma unroll
        for (int u = 0; u < 8; u++) {
            int ks = u >> 1, reg = u & 1;
            int c0 = ks * 16 + reg * 8 + cv_cbase;
            float v0 = 0.0f, v1 = 0.0f;
            if (cv_pos < nvalid) {
                v0 = xb[c0 * (TFULL * VD) + cv_pos];
                v1 = xb[(c0 + 1) * (TFULL * VD) + cv_pos];
            }
            __nv_bfloat16 h0 = __float2bfloat16(v0), h1 = __float2bfloat16(v1);
            float h0f = __bfloat162float(h0), h1f = __bfloat162float(h1);
            int off = xb_off(w * 4 + ks, reg, lane);
            *reinterpret_cast<uint32_t*>(smem + OFF_XBH + off) = pack2bf(h0f, h1f);
            *reinterpret_cast<uint32_t*>(smem + OFF_XBL + off) = pack2bf(v0 - h0f, v1 - h1f);
        }
    }
    __syncthreads();

    for (int rel = 0; rel < TILES_PER_CTA; rel++) {
        const int tile = tile0 + rel;
        const int n  = tile / TILES_PER_N;
        const int j  = tile - n * TILES_PER_N;
        const int t0 = j * TT;
        const int valid_t = (t0 + TT <= TFULL) ? TT : (TFULL - t0);

        // ============ phase 1: stage A GEMM (4x4 blocking) + repack ==========
        {
            const int sg = w >> 2;   // strips {sg, sg+4, sg+8}
            const int pg = w & 3;    // posblks {pg, pg+4, pg+8, pg+12}

            // hoist X B-frags for this warp's 4 posblks (SoA reads, 64 regs)
            uint2 xbh[4][4], xbl[4][4];
#pragma unroll
            for (int p_i = 0; p_i < 4; p_i++) {
                int pb = pg + 4 * p_i;
#pragma unroll
                for (int ks = 0; ks < 4; ks++) {
                    int f = pb * 4 + ks;
                    xbh[p_i][ks].x = *reinterpret_cast<const uint32_t*>(smem + OFF_XBH + xb_off(f, 0, lane));
                    xbh[p_i][ks].y = *reinterpret_cast<const uint32_t*>(smem + OFF_XBH + xb_off(f, 1, lane));
                    xbl[p_i][ks].x = *reinterpret_cast<const uint32_t*>(smem + OFF_XBL + xb_off(f, 0, lane));
                    xbl[p_i][ks].y = *reinterpret_cast<const uint32_t*>(smem + OFF_XBL + xb_off(f, 1, lane));
                }
            }
#pragma unroll
            for (int s_i = 0; s_i < 3; s_i++) {
                const int s = sg + 4 * s_i;
                uint4 ah[4], al[4];
#pragma unroll
                for (int ks = 0; ks < 4; ks++) {
                    ah[ks] = *reinterpret_cast<const uint4*>(
                        smem + OFF_WAH + (((s * 4 + ks) * 32 + lane) << 4));
                    al[ks] = *reinterpret_cast<const uint4*>(
                        smem + OFF_WAL + (((s * 4 + ks) * 32 + lane) << 4));
                }
                const int rowA0 = s * 16 + g;
                const int k0 = rowA0 >> 6, o0 = rowA0 & 63;
                const int rowA1 = rowA0 + 8;
                const int k1 = rowA1 >> 6, o1 = rowA1 & 63;
#pragma unroll
                for (int p_i = 0; p_i < 4; p_i++) {
                    const int pb = pg + 4 * p_i;
                    const int p0 = pb * 8 + 2 * tig;
                    float D[4] = {0.0f, 0.0f, 0.0f, 0.0f};
#pragma unroll
                    for (int ks = 0; ks < 4; ks++) {
                        mma_bf16(D, ah[ks].x, ah[ks].y, ah[ks].z, ah[ks].w,
                                 xbh[p_i][ks].x, xbh[p_i][ks].y);
                        mma_bf16(D, ah[ks].x, ah[ks].y, ah[ks].z, ah[ks].w,
                                 xbl[p_i][ks].x, xbl[p_i][ks].y);
                        mma_bf16(D, al[ks].x, al[ks].y, al[ks].z, al[ks].w,
                                 xbh[p_i][ks].x, xbh[p_i][ks].y);
                    }
                    if (p0 < 126) {
                        int tloc = (p0 * 228) >> 12;
                        int vloc = p0 - 18 * tloc;
                        ya_write(tloc * 64 + o0, k0 * 18 + vloc, D[0], D[1]);
                        ya_write(tloc * 64 + o1, k1 * 18 + vloc, D[2], D[3]);
                    }
                }
            }
        }
        __syncthreads();

        // ====== phase 2: LDG(next) | stage B GEMM + relu/store | STS(next) ==
        const bool hasNext = (rel + 1 < TILES_PER_CTA);
        float pf[16];
        int nxt_nvalid = 0;
        if (hasNext) {
            int tn = tile + 1;
            int nn = tn / TILES_PER_N;
            int jn = tn - nn * TILES_PER_N;
            int tn0 = jn * TT;
            nxt_nvalid = ((tn0 + TT <= TFULL) ? TT : (TFULL - tn0)) * VD;
            const float* xb = x + (size_t)nn * (CIN * TFULL * VD) + (size_t)tn0 * VD;
#pragma unroll
            for (int u = 0; u < 8; u++) {
                int ks = u >> 1, reg = u & 1;
                int c0 = ks * 16 + reg * 8 + cv_cbase;
                bool okp = (cv_pos < nxt_nvalid);
                pf[2 * u]     = okp ? __ldg(xb + c0 * (TFULL * VD) + cv_pos) : 0.0f;
                pf[2 * u + 1] = okp ? __ldg(xb + (c0 + 1) * (TFULL * VD) + cv_pos) : 0.0f;
            }
        }

        // ---- stage B: M' frags hoisted (48 regs), strips {w, w+16} ----
        {
            uint2 mbh[3][4], mbl[3][4];
#pragma unroll
            for (int nb = 0; nb < 3; nb++)
#pragma unroll
                for (int ks = 0; ks < 4; ks++) {
                    mbh[nb][ks] = *reinterpret_cast<const uint2*>(
                        smem + OFF_MBH + (((nb * 4 + ks) * 32 + lane) << 3));
                    mbl[nb][ks] = *reinterpret_cast<const uint2*>(
                        smem + OFF_MBL + (((nb * 4 + ks) * 32 + lane) << 3));
                }
            for (int si = w; si < 28; si += 16) {
                uint4 ah[4], al[4];
#pragma unroll
                for (int ks = 0; ks < 4; ks++) {
                    int f = si * 4 + ks;
                    ah[ks].x = *reinterpret_cast<const uint32_t*>(smem + OFF_YAH + ya_off(f, 0, lane));
                    ah[ks].y = *reinterpret_cast<const uint32_t*>(smem + OFF_YAH + ya_off(f, 1, lane));
                    ah[ks].z = *reinterpret_cast<const uint32_t*>(smem + OFF_YAH + ya_off(f, 2, lane));
                    ah[ks].w = *reinterpret_cast<const uint32_t*>(smem + OFF_YAH + ya_off(f, 3, lane));
                    al[ks].x = *reinterpret_cast<const uint32_t*>(smem + OFF_YAL + ya_off(f, 0, lane));
                    al[ks].y = *reinterpret_cast<const uint32_t*>(smem + OFF_YAL + ya_off(f, 1, lane));
                    al[ks].z = *reinterpret_cast<const uint32_t*>(smem + OFF_YAL + ya_off(f, 2, lane));
                    al[ks].w = *reinterpret_cast<const uint32_t*>(smem + OFF_YAL + ya_off(f, 3, lane));
                }
                const int rowB = si * 16 + g;
                const int tB = rowB >> 6;
                const int oB = rowB & 63;
#pragma unroll
                for (int nb = 0; nb < 3; nb++) {
                    float D2[4] = {0.0f, 0.0f, 0.0f, 0.0f};
#pragma unroll
                    for (int ks = 0; ks < 4; ks++) {
                        mma_bf16(D2, ah[ks].x, ah[ks].y, ah[ks].z, ah[ks].w,
                                 mbh[nb][ks].x, mbh[nb][ks].y);
                        mma_bf16(D2, ah[ks].x, ah[ks].y, ah[ks].z, ah[ks].w,
                                 mbl[nb][ks].x, mbl[nb][ks].y);
                        mma_bf16(D2, al[ks].x, al[ks].y, al[ks].z, al[ks].w,
                                 mbh[nb][ks].x, mbh[nb][ks].y);
                    }
                    int w0 = nb * 8 + 2 * tig;
                    if (w0 < VD && tB < valid_t) {
                        size_t base = ((size_t)(n * 64 + oB) * TFULL + (t0 + tB)) * VD + w0;
                        *reinterpret_cast<float2*>(out + base) =
                            make_float2(fmaxf(D2[0], 0.0f), fmaxf(D2[1], 0.0f));
                        size_t base2 = base + (size_t)8 * TFULL * VD;   // o+8
                        *reinterpret_cast<float2*>(out + base2) =
                            make_float2(fmaxf(D2[2], 0.0f), fmaxf(D2[3], 0.0f));
                    }
                }
            }
        }

        // ---- convert next tile into X B-frags (SoA) ----
        if (hasNext) {
#pragma unroll
            for (int u = 0; u < 8; u++) {
                int ks = u >> 1, reg = u & 1;
                float v0 = pf[2 * u], v1 = pf[2 * u + 1];
                __nv_bfloat16 h0 = __float2bfloat16(v0), h1 = __float2bfloat16(v1);
                float h0f = __bfloat162float(h0), h1f = __bfloat162float(h1);
                int off = xb_off(w * 4 + ks, reg, lane);
                *reinterpret_cast<uint32_t*>(smem + OFF_XBH + off) = pack2bf(h0f, h1f);
                *reinterpret_cast<uint32_t*>(smem + OFF_XBL + off) = pack2bf(v0 - h0f, v1 - h1f);
            }
        }
        __syncthreads();
    }
}

extern "C" void kernel_launch(void* const* d_in, const int* in_sizes, int n_in,
                              void* d_out, int out_size)
{
    (void)in_sizes; (void)n_in; (void)out_size;
    const float* x    = (const float*)d_in[0];
    const float* A    = (const float*)d_in[1];
    const float* PA   = (const float*)d_in[2];
    const float* Wta  = (const float*)d_in[3];
    const float* bta  = (const float*)d_in[4];
    const float* g_ta = (const float*)d_in[5];
    const float* b_ta = (const float*)d_in[6];
    const float* m_ta = (const float*)d_in[7];
    const float* v_ta = (const float*)d_in[8];
    // d_in[9..12] dead attention branch
    const float* g_bn = (const float*)d_in[13];
    const float* b_bn = (const float*)d_in[14];
    const float* m_bn = (const float*)d_in[15];
    const float* v_bn = (const float*)d_in[16];
    float* out = (float*)d_out;

    cudaFuncSetAttribute(ctrgc16, cudaFuncAttributeMaxDynamicSharedMemorySize, SMEM_BYTES);

    prep_kernel<<<1, 256>>>(A, PA, Wta, bta, g_ta, b_ta, m_ta, v_ta,
                            g_bn, b_bn, m_bn, v_bn);
    ctrgc16<<<GRID, THREADS, SMEM_BYTES>>>(x, out);
}